// round 1
// baseline (speedup 1.0000x reference)
#include <cuda_runtime.h>

// ---------------- problem dimensions (fixed by the dataset) ----------------
#define B_IMG   8
#define N_PRED  100
#define T_TGT   160
#define M_TGT   20
#define K_CLS   80
#define HW      25600
#define BN_ROWS 800          // B_IMG * N_PRED

// ---------------- GEMM tiling ----------------
#define BM      64
#define BK      16
#define KSPLIT  16
#define KCHUNK  1600         // HW / KSPLIT
#define AS_LD   68           // padded lds stride (floats), keeps 16B alignment
#define BS_LD   162          // padded, keeps 8B alignment for float2 reads

// ---------------- scratch (no allocations allowed) ----------------
__device__ float g_partial[KSPLIT * BN_ROWS * T_TGT];   // 8.19 MB
__device__ float g_pn[BN_ROWS];
__device__ float g_tn[T_TGT];

// ---------------- packed fp32x2 helpers (Blackwell) ----------------
__device__ __forceinline__ unsigned long long pack_dup(float a) {
    unsigned long long r; unsigned ai = __float_as_uint(a);
    asm("mov.b64 %0, {%1, %1};" : "=l"(r) : "r"(ai));
    return r;
}
__device__ __forceinline__ void ffma2(unsigned long long& d, unsigned long long a, unsigned long long b) {
    asm("fma.rn.f32x2 %0, %1, %2, %3;" : "=l"(d) : "l"(a), "l"(b), "l"(d));
}

// ---------------- row sum-of-squares (deterministic) ----------------
__global__ void __launch_bounds__(256) row_sumsq_kernel(const float* __restrict__ x,
                                                        float* __restrict__ out,
                                                        int rowlen)
{
    const int r = blockIdx.x;
    const int tid = threadIdx.x;
    const float4* xr = (const float4*)(x + (size_t)r * rowlen);
    const int n4 = rowlen >> 2;
    float s = 0.f;
    for (int i = tid; i < n4; i += 256) {
        float4 v = xr[i];
        s += v.x * v.x + v.y * v.y + v.z * v.z + v.w * v.w;
    }
    __shared__ float red[256];
    red[tid] = s;
    __syncthreads();
    for (int o = 128; o > 0; o >>= 1) {
        if (tid < o) red[tid] += red[tid + o];
        __syncthreads();
    }
    if (tid == 0) out[r] = red[0];
}

// ---------------- split-K fp32x2 GEMM: P[ks] += A(64 rows) . B^T (160 cols) ----------------
__global__ void __launch_bounds__(256) gemm_kernel(const float* __restrict__ A,
                                                   const float* __restrict__ Bm,
                                                   float* __restrict__ P)
{
    __shared__ __align__(16) float As[BK][AS_LD];   // [k][m]
    __shared__ __align__(16) float Bs[BK][BS_LD];   // [k][n]

    const int tid     = threadIdx.x;
    const int rowBase = blockIdx.x * BM;
    const int kBase   = blockIdx.y * KCHUNK;
    const int tr      = tid >> 4;     // 0..15 -> rows tr*4..tr*4+3
    const int tc      = tid & 15;     // 0..15 -> cols tc*10..tc*10+9

    unsigned long long acc[4][5];
#pragma unroll
    for (int r = 0; r < 4; r++)
#pragma unroll
        for (int c = 0; c < 5; c++) acc[r][c] = 0ULL;

    // A-tile loader mapping: one float4 along k per thread
    const int a_row  = tid >> 2;            // 0..63
    const int a_k    = (tid & 3) << 2;      // 0,4,8,12
    const int garow  = rowBase + a_row;
    const bool a_ok  = (garow < BN_ROWS);
    const float* Aptr = A + (size_t)garow * HW + kBase + a_k;

    // B-tile loader mapping: 640 float4 across 256 threads (2 full + 1 partial)
    const int f0 = tid, f1 = tid + 256, f2 = tid + 512;
    const int brow0 = f0 >> 2, bk0 = (f0 & 3) << 2;
    const int brow1 = f1 >> 2, bk1 = (f1 & 3) << 2;
    const int brow2 = f2 >> 2, bk2 = (f2 & 3) << 2;
    const bool b2ok = (f2 < 640);

    for (int kt = 0; kt < KCHUNK / BK; ++kt) {
        const int k0 = kBase + kt * BK;
        float4 av = make_float4(0.f, 0.f, 0.f, 0.f);
        if (a_ok) av = *(const float4*)(Aptr + kt * BK);
        float4 bv0 = *(const float4*)&Bm[(size_t)brow0 * HW + k0 + bk0];
        float4 bv1 = *(const float4*)&Bm[(size_t)brow1 * HW + k0 + bk1];
        float4 bv2 = make_float4(0.f, 0.f, 0.f, 0.f);
        if (b2ok) bv2 = *(const float4*)&Bm[(size_t)brow2 * HW + k0 + bk2];

        __syncthreads();   // previous tile fully consumed
        As[a_k + 0][a_row] = av.x; As[a_k + 1][a_row] = av.y;
        As[a_k + 2][a_row] = av.z; As[a_k + 3][a_row] = av.w;
        Bs[bk0 + 0][brow0] = bv0.x; Bs[bk0 + 1][brow0] = bv0.y;
        Bs[bk0 + 2][brow0] = bv0.z; Bs[bk0 + 3][brow0] = bv0.w;
        Bs[bk1 + 0][brow1] = bv1.x; Bs[bk1 + 1][brow1] = bv1.y;
        Bs[bk1 + 2][brow1] = bv1.z; Bs[bk1 + 3][brow1] = bv1.w;
        if (b2ok) {
            Bs[bk2 + 0][brow2] = bv2.x; Bs[bk2 + 1][brow2] = bv2.y;
            Bs[bk2 + 2][brow2] = bv2.z; Bs[bk2 + 3][brow2] = bv2.w;
        }
        __syncthreads();

#pragma unroll
        for (int k = 0; k < BK; ++k) {
            float4 af = *(const float4*)&As[k][tr << 2];
            unsigned long long ap0 = pack_dup(af.x);
            unsigned long long ap1 = pack_dup(af.y);
            unsigned long long ap2 = pack_dup(af.z);
            unsigned long long ap3 = pack_dup(af.w);
            unsigned long long bp[5];
#pragma unroll
            for (int c = 0; c < 5; c++)
                bp[c] = *(const unsigned long long*)&Bs[k][tc * 10 + c * 2];
#pragma unroll
            for (int c = 0; c < 5; c++) {
                ffma2(acc[0][c], ap0, bp[c]);
                ffma2(acc[1][c], ap1, bp[c]);
                ffma2(acc[2][c], ap2, bp[c]);
                ffma2(acc[3][c], ap3, bp[c]);
            }
        }
    }

    float* dst = P + (size_t)blockIdx.y * (BN_ROWS * T_TGT);
#pragma unroll
    for (int r = 0; r < 4; r++) {
        int row = rowBase + (tr << 2) + r;
        if (row < BN_ROWS) {
#pragma unroll
            for (int c = 0; c < 5; c++)
                *(unsigned long long*)&dst[(size_t)row * T_TGT + tc * 10 + c * 2] = acc[r][c];
        }
    }
}

// ---------------- finalize: dice + focal -> C ----------------
__global__ void __launch_bounds__(256) finalize_kernel(const float* __restrict__ P,
                                                       const float* __restrict__ pn,
                                                       const float* __restrict__ tn,
                                                       const float* __restrict__ logits,
                                                       const int*   __restrict__ ids,
                                                       float* __restrict__ C)
{
    const int idx = blockIdx.x * 256 + threadIdx.x;
    if (idx >= BN_ROWS * T_TGT) return;
    const int bn = idx / T_TGT;
    const int t  = idx - bn * T_TGT;

    float dot = 0.f;
#pragma unroll
    for (int ks = 0; ks < KSPLIT; ks++)
        dot += P[(size_t)ks * (BN_ROWS * T_TGT) + idx];

    const float den = pn[bn] + tn[t];
    const float score = -((2.0f * dot + 1e-4f) / (den + 1e-4f));   // dice score cost

    const int id = ids[t];
    const float x = logits[bn * K_CLS + id];
    float pl;
    if (x >= 0.f) pl = 1.f / (1.f + expf(-x));
    else { float e = expf(x); pl = e / (1.f + e); }
    const float pos = 0.25f * (1.f - pl) * (1.f - pl) * (-logf(pl + 1e-8f));
    const float neg = 0.75f * pl * pl * (-logf(1.f - pl + 1e-8f));

    C[idx] = score * 2.0f + (pos - neg);
}

// ---------------- Jonker-Volgenant LSA, one warp per image ----------------
// Exactly mirrors the reference: cost slice (100 preds x 20 targets) is transposed
// to n=20 rows (targets) x m=100 cols (preds); float64 potentials.
__device__ __forceinline__ unsigned long long dkey(double d) {
    long long b = __double_as_longlong(d);
    return (unsigned long long)(b >= 0 ? (b ^ 0x8000000000000000LL) : ~b);
}
__device__ __forceinline__ double inv_dkey(unsigned long long k) {
    long long b = (k & 0x8000000000000000ULL) ? (long long)(k ^ 0x8000000000000000ULL)
                                              : ~(long long)k;
    return __longlong_as_double(b);
}

__global__ void __launch_bounds__(32) lsa_kernel(const float* __restrict__ C,
                                                 float* __restrict__ out_rows,
                                                 float* __restrict__ out_cols)
{
    const int b    = blockIdx.x;
    const int lane = threadIdx.x;
    const double INFD = 1e18;

    __shared__ float  c[M_TGT][N_PRED];     // c[t][pred]
    __shared__ double u[M_TGT + 1], v[N_PRED + 1], minv[N_PRED + 1];
    __shared__ int    p[N_PRED + 1], way[N_PRED + 1], used[N_PRED + 1];

    // load transposed block-diagonal slice
    for (int idx = lane; idx < M_TGT * N_PRED; idx += 32) {
        int t = idx / N_PRED, n = idx - t * N_PRED;
        c[t][n] = C[(size_t)b * (N_PRED * T_TGT) + (size_t)n * T_TGT + b * M_TGT + t];
    }
    for (int j = lane; j <= N_PRED; j += 32) { v[j] = 0.0; p[j] = 0; way[j] = 0; }
    if (lane <= M_TGT) u[lane] = 0.0;
    __syncwarp();

    for (int i = 1; i <= M_TGT; ++i) {
        if (lane == 0) p[0] = i;
        for (int j = lane; j <= N_PRED; j += 32) { minv[j] = INFD; used[j] = 0; }
        __syncwarp();

        int j0 = 0;
        while (true) {
            if (lane == 0) used[j0] = 1;
            __syncwarp();
            const int i0 = p[j0];
            const double ui0 = u[i0];

            // relax owned columns + local argmin (first index wins ties)
            unsigned long long bestKey = 0xFFFFFFFFFFFFFFFFULL;
            int bestJ = N_PRED + 1;
#pragma unroll
            for (int q = 0; q < 4; q++) {
                int j = lane + q * 32;
                if (j >= 1 && j <= N_PRED && !used[j]) {
                    double cur = ((double)c[i0 - 1][j - 1] - ui0) - v[j];
                    double mj = minv[j];
                    if (cur < mj) { minv[j] = cur; way[j] = j0; mj = cur; }
                    unsigned long long key = dkey(mj);
                    if (key < bestKey) { bestKey = key; bestJ = j; }
                }
            }
            // warp argmin on (key, j) — smaller key, then smaller j
            for (int off = 16; off > 0; off >>= 1) {
                unsigned long long k2 = __shfl_down_sync(0xffffffff, bestKey, off);
                int j2 = __shfl_down_sync(0xffffffff, bestJ, off);
                if (k2 < bestKey || (k2 == bestKey && j2 < bestJ)) { bestKey = k2; bestJ = j2; }
            }
            bestKey = __shfl_sync(0xffffffff, bestKey, 0);
            bestJ   = __shfl_sync(0xffffffff, bestJ, 0);
            const int j1 = bestJ;
            const double delta = inv_dkey(bestKey);

            __syncwarp();   // all reads of u/v done before updates
#pragma unroll
            for (int q = 0; q < 4; q++) {
                int j = lane + q * 32;
                if (j <= N_PRED) {
                    if (used[j]) { u[p[j]] += delta; v[j] -= delta; }
                    else         { minv[j] -= delta; }
                }
            }
            __syncwarp();

            j0 = j1;
            if (p[j0] == 0) break;
        }

        // augmenting path (sequential, tiny)
        if (lane == 0) {
            int jj = j0;
            while (jj != 0) { int jn = way[jj]; p[jj] = p[jn]; jj = jn; }
        }
        __syncwarp();
    }

    if (lane == 0) {
        int k = 0;
        for (int j = 1; j <= N_PRED; j++) {
            if (p[j] != 0) {
                out_rows[b * M_TGT + k] = (float)(j - 1);      // pred index (ascending)
                out_cols[b * M_TGT + k] = (float)(p[j] - 1);   // matched target index
                k++;
            }
        }
    }
}

// ---------------- launch ----------------
extern "C" void kernel_launch(void* const* d_in, const int* in_sizes, int n_in,
                              void* d_out, int out_size)
{
    const float* pred_masks   = (const float*)d_in[0];   // (8,100,160,160)
    const float* pred_logits  = (const float*)d_in[1];   // (8,100,80)
    const float* target_masks = (const float*)d_in[2];   // (160,160,160)
    const int*   tgt_ids      = (const int*)d_in[3];     // (160,)
    float* out = (float*)d_out;                          // [C | rows | cols]

    float* d_partial; cudaGetSymbolAddress((void**)&d_partial, g_partial);
    float* d_pn;      cudaGetSymbolAddress((void**)&d_pn, g_pn);
    float* d_tn;      cudaGetSymbolAddress((void**)&d_tn, g_tn);

    row_sumsq_kernel<<<BN_ROWS, 256>>>(pred_masks, d_pn, HW);
    row_sumsq_kernel<<<T_TGT, 256>>>(target_masks, d_tn, HW);

    dim3 ggrid((BN_ROWS + BM - 1) / BM, KSPLIT);
    gemm_kernel<<<ggrid, 256>>>(pred_masks, target_masks, d_partial);

    finalize_kernel<<<(BN_ROWS * T_TGT) / 256, 256>>>(d_partial, d_pn, d_tn,
                                                      pred_logits, tgt_ids, out);

    lsa_kernel<<<B_IMG, 32>>>(out,
                              out + BN_ROWS * T_TGT,
                              out + BN_ROWS * T_TGT + B_IMG * M_TGT);
}

// round 3
// speedup vs baseline: 2.3408x; 2.3408x over previous
#include <cuda_runtime.h>
#include <cstdint>

// ---------------- problem dimensions (fixed by the dataset) ----------------
#define B_IMG   8
#define N_PRED  100
#define T_TGT   160
#define M_TGT   20
#define K_CLS   80
#define HW      25600
#define BN_ROWS 800

// ---------------- mma.sync tf32 GEMM tiling ----------------
#define KSPLIT  20
#define KCHUNK  1280             // HW / KSPLIT
#define BK      16
#define NIT     (KCHUNK / BK)    // 80
#define MTILE   128
#define MBLKS   7                // ceil(800/128)
#define LDA_S   20               // smem row stride in floats (16 + 4 pad)

// ---------------- scratch (no allocations allowed) ----------------
__device__ float g_partial[KSPLIT * BN_ROWS * T_TGT];   // 10.24 MB, [ks][row][col]
__device__ float g_pn[BN_ROWS];
__device__ float g_tn[T_TGT];

// ---------------- helpers ----------------
__device__ __forceinline__ uint32_t smem_u32(const void* p) {
    uint32_t a;
    asm("{ .reg .u64 t; cvta.to.shared.u64 t, %1; cvt.u32.u64 %0, t; }" : "=r"(a) : "l"(p));
    return a;
}
__device__ __forceinline__ void cp16(uint32_t dst, const void* src, int sz) {
    asm volatile("cp.async.cg.shared.global [%0], [%1], 16, %2;"
                 :: "r"(dst), "l"(src), "r"(sz) : "memory");
}
__device__ __forceinline__ void cp_commit() {
    asm volatile("cp.async.commit_group;" ::: "memory");
}
__device__ __forceinline__ void mma_tf32(float* c, const uint32_t* a, const uint32_t* b) {
    asm volatile(
        "mma.sync.aligned.m16n8k8.row.col.f32.tf32.tf32.f32 "
        "{%0,%1,%2,%3}, {%4,%5,%6,%7}, {%8,%9}, {%0,%1,%2,%3};"
        : "+f"(c[0]), "+f"(c[1]), "+f"(c[2]), "+f"(c[3])
        : "r"(a[0]), "r"(a[1]), "r"(a[2]), "r"(a[3]), "r"(b[0]), "r"(b[1]));
}

// ---------------- row sum-of-squares (deterministic) ----------------
__global__ void __launch_bounds__(256) row_sumsq_kernel(const float* __restrict__ x,
                                                        float* __restrict__ out,
                                                        int rowlen)
{
    const int r = blockIdx.x;
    const int tid = threadIdx.x;
    const float4* xr = (const float4*)(x + (size_t)r * rowlen);
    const int n4 = rowlen >> 2;
    float s = 0.f;
    for (int i = tid; i < n4; i += 256) {
        float4 v = xr[i];
        s += v.x * v.x + v.y * v.y + v.z * v.z + v.w * v.w;
    }
    __shared__ float red[256];
    red[tid] = s;
    __syncthreads();
    for (int o = 128; o > 0; o >>= 1) {
        if (tid < o) red[tid] += red[tid + o];
        __syncthreads();
    }
    if (tid == 0) out[r] = red[0];
}

// ---------------- tf32 mma.sync split-K GEMM ----------------
// P[ks][row][col] = A[row, kChunk] . B[col, kChunk]^T
__global__ void __launch_bounds__(256, 1)
gemm_mma_kernel(const float* __restrict__ A, const float* __restrict__ Bm,
                float* __restrict__ P)
{
    __shared__ __align__(16) float As[2][MTILE * LDA_S];   // [m][k], 10240 B each
    __shared__ __align__(16) float Bs[2][T_TGT * LDA_S];   // [n][k], 12800 B each

    const int tid   = threadIdx.x;
    const int wid   = tid >> 5;
    const int lane  = tid & 31;
    const int gid   = lane >> 2;     // 0..7
    const int tig   = lane & 3;      // 0..3
    const int warpM = wid >> 1;      // 0..3 -> 32 rows each
    const int warpN = wid & 1;       // 0..1 -> 80 cols each
    const int mBase = blockIdx.x * MTILE;
    const int kBase = blockIdx.y * KCHUNK;

    float acc[2][10][4];
#pragma unroll
    for (int tm = 0; tm < 2; tm++)
#pragma unroll
        for (int tn = 0; tn < 10; tn++)
#pragma unroll
            for (int i = 0; i < 4; i++) acc[tm][tn][i] = 0.f;

    const uint32_t sA[2] = { smem_u32(As[0]), smem_u32(As[1]) };
    const uint32_t sB[2] = { smem_u32(Bs[0]), smem_u32(Bs[1]) };

    // ---- async tile loader ----
    // A: 512 16B chunks (tid*2, tid*2+1); B: 640 chunks (tid, tid+256, tid+512 if tid<128)
    auto issue = [&](int t) {
        const int buf = t & 1;
        const int kOff = kBase + t * BK;
#pragma unroll
        for (int i = 0; i < 2; ++i) {
            const int f = tid * 2 + i;
            const int row = f >> 2, kq = f & 3;
            const int grow = mBase + row;
            const int ok = grow < BN_ROWS;
            const float* src = A + (size_t)(ok ? grow : 0) * HW + kOff + kq * 4;
            cp16(sA[buf] + row * (LDA_S * 4) + kq * 16, src, ok ? 16 : 0);
        }
#pragma unroll
        for (int i = 0; i < 3; ++i) {
            const int f = tid + i * 256;
            if (f < T_TGT * 4) {
                const int row = f >> 2, kq = f & 3;
                cp16(sB[buf] + row * (LDA_S * 4) + kq * 16,
                     Bm + (size_t)row * HW + kOff + kq * 4, 16);
            }
        }
        cp_commit();
    };

    issue(0);

    for (int t = 0; t < NIT; ++t) {
        if (t + 1 < NIT) {
            issue(t + 1);
            asm volatile("cp.async.wait_group 1;" ::: "memory");
        } else {
            asm volatile("cp.async.wait_group 0;" ::: "memory");
        }
        __syncthreads();

        const int buf = t & 1;
        const uint32_t* as = (const uint32_t*)As[buf];
        const uint32_t* bs = (const uint32_t*)Bs[buf];

#pragma unroll
        for (int s = 0; s < 2; ++s) {           // two k=8 steps per BK=16
            uint32_t af[2][4], bf[10][2];
#pragma unroll
            for (int tm = 0; tm < 2; tm++) {
                const int r0 = warpM * 32 + tm * 16 + gid;
                const int k0 = s * 8 + tig;
                af[tm][0] = as[r0 * LDA_S + k0];
                af[tm][1] = as[(r0 + 8) * LDA_S + k0];
                af[tm][2] = as[r0 * LDA_S + k0 + 4];
                af[tm][3] = as[(r0 + 8) * LDA_S + k0 + 4];
            }
#pragma unroll
            for (int tn = 0; tn < 10; tn++) {
                const int n = warpN * 80 + tn * 8 + gid;
                const int k0 = s * 8 + tig;
                bf[tn][0] = bs[n * LDA_S + k0];
                bf[tn][1] = bs[n * LDA_S + k0 + 4];
            }
#pragma unroll
            for (int tm = 0; tm < 2; tm++)
#pragma unroll
                for (int tn = 0; tn < 10; tn++)
                    mma_tf32(acc[tm][tn], af[tm], bf[tn]);
        }
        __syncthreads();
    }

    // ---- epilogue: write P[ks][row][col] ----
    float* dst = P + (size_t)blockIdx.y * (BN_ROWS * T_TGT);
#pragma unroll
    for (int tm = 0; tm < 2; tm++) {
        const int r0 = mBase + warpM * 32 + tm * 16 + gid;
        const int r1 = r0 + 8;
#pragma unroll
        for (int tn = 0; tn < 10; tn++) {
            const int col = warpN * 80 + tn * 8 + tig * 2;
            if (r0 < BN_ROWS)
                *(float2*)&dst[(size_t)r0 * T_TGT + col] = make_float2(acc[tm][tn][0], acc[tm][tn][1]);
            if (r1 < BN_ROWS)
                *(float2*)&dst[(size_t)r1 * T_TGT + col] = make_float2(acc[tm][tn][2], acc[tm][tn][3]);
        }
    }
}

// ---------------- finalize: dice + focal -> C ----------------
__global__ void __launch_bounds__(256) finalize_kernel(const float* __restrict__ P,
                                                       const float* __restrict__ pn,
                                                       const float* __restrict__ tn,
                                                       const float* __restrict__ logits,
                                                       const int*   __restrict__ ids,
                                                       float* __restrict__ C)
{
    const int idx = blockIdx.x * 256 + threadIdx.x;
    if (idx >= BN_ROWS * T_TGT) return;
    const int bn = idx / T_TGT;
    const int t  = idx - bn * T_TGT;

    float dot = 0.f;
#pragma unroll
    for (int ks = 0; ks < KSPLIT; ks++)
        dot += P[(size_t)ks * (BN_ROWS * T_TGT) + idx];

    const float den = pn[bn] + tn[t];
    const float score = -((2.0f * dot + 1e-4f) / (den + 1e-4f));   // dice score cost

    const int id = ids[t];
    const float x = logits[bn * K_CLS + id];
    float pl;
    if (x >= 0.f) pl = 1.f / (1.f + expf(-x));
    else { float e = expf(x); pl = e / (1.f + e); }
    const float pos = 0.25f * (1.f - pl) * (1.f - pl) * (-logf(pl + 1e-8f));
    const float neg = 0.75f * pl * pl * (-logf(1.f - pl + 1e-8f));

    C[idx] = score * 2.0f + (pos - neg);
}

// ---------------- Jonker-Volgenant LSA, one warp per image ----------------
__device__ __forceinline__ unsigned long long dkey(double d) {
    long long b = __double_as_longlong(d);
    return (unsigned long long)(b >= 0 ? (b ^ 0x8000000000000000LL) : ~b);
}
__device__ __forceinline__ double inv_dkey(unsigned long long k) {
    long long b = (k & 0x8000000000000000ULL) ? (long long)(k ^ 0x8000000000000000ULL)
                                              : ~(long long)k;
    return __longlong_as_double(b);
}

__global__ void __launch_bounds__(32) lsa_kernel(const float* __restrict__ C,
                                                 float* __restrict__ out_rows,
                                                 float* __restrict__ out_cols)
{
    const int b    = blockIdx.x;
    const int lane = threadIdx.x;
    const double INFD = 1e18;

    __shared__ float  c[M_TGT][N_PRED];     // c[t][pred]
    __shared__ double u[M_TGT + 1], v[N_PRED + 1], minv[N_PRED + 1];
    __shared__ int    p[N_PRED + 1], way[N_PRED + 1], used[N_PRED + 1];

    for (int idx = lane; idx < M_TGT * N_PRED; idx += 32) {
        int t = idx / N_PRED, n = idx - t * N_PRED;
        c[t][n] = C[(size_t)b * (N_PRED * T_TGT) + (size_t)n * T_TGT + b * M_TGT + t];
    }
    for (int j = lane; j <= N_PRED; j += 32) { v[j] = 0.0; p[j] = 0; way[j] = 0; }
    if (lane <= M_TGT) u[lane] = 0.0;
    __syncwarp();

    for (int i = 1; i <= M_TGT; ++i) {
        if (lane == 0) p[0] = i;
        for (int j = lane; j <= N_PRED; j += 32) { minv[j] = INFD; used[j] = 0; }
        __syncwarp();

        int j0 = 0;
        while (true) {
            if (lane == 0) used[j0] = 1;
            __syncwarp();
            const int i0 = p[j0];
            const double ui0 = u[i0];

            unsigned long long bestKey = 0xFFFFFFFFFFFFFFFFULL;
            int bestJ = N_PRED + 1;
#pragma unroll
            for (int q = 0; q < 4; q++) {
                int j = lane + q * 32;
                if (j >= 1 && j <= N_PRED && !used[j]) {
                    double cur = ((double)c[i0 - 1][j - 1] - ui0) - v[j];
                    double mj = minv[j];
                    if (cur < mj) { minv[j] = cur; way[j] = j0; mj = cur; }
                    unsigned long long key = dkey(mj);
                    if (key < bestKey) { bestKey = key; bestJ = j; }
                }
            }
            for (int off = 16; off > 0; off >>= 1) {
                unsigned long long k2 = __shfl_down_sync(0xffffffff, bestKey, off);
                int j2 = __shfl_down_sync(0xffffffff, bestJ, off);
                if (k2 < bestKey || (k2 == bestKey && j2 < bestJ)) { bestKey = k2; bestJ = j2; }
            }
            bestKey = __shfl_sync(0xffffffff, bestKey, 0);
            bestJ   = __shfl_sync(0xffffffff, bestJ, 0);
            const int j1 = bestJ;
            const double delta = inv_dkey(bestKey);

            __syncwarp();
#pragma unroll
            for (int q = 0; q < 4; q++) {
                int j = lane + q * 32;
                if (j <= N_PRED) {
                    if (used[j]) { u[p[j]] += delta; v[j] -= delta; }
                    else         { minv[j] -= delta; }
                }
            }
            __syncwarp();

            j0 = j1;
            if (p[j0] == 0) break;
        }

        if (lane == 0) {
            int jj = j0;
            while (jj != 0) { int jn = way[jj]; p[jj] = p[jn]; jj = jn; }
        }
        __syncwarp();
    }

    if (lane == 0) {
        int k = 0;
        for (int j = 1; j <= N_PRED; j++) {
            if (p[j] != 0) {
                out_rows[b * M_TGT + k] = (float)(j - 1);
                out_cols[b * M_TGT + k] = (float)(p[j] - 1);
                k++;
            }
        }
    }
}

// ---------------- launch ----------------
extern "C" void kernel_launch(void* const* d_in, const int* in_sizes, int n_in,
                              void* d_out, int out_size)
{
    const float* pred_masks   = (const float*)d_in[0];   // (8,100,160,160)
    const float* pred_logits  = (const float*)d_in[1];   // (8,100,80)
    const float* target_masks = (const float*)d_in[2];   // (160,160,160)
    const int*   tgt_ids      = (const int*)d_in[3];     // (160,)
    float* out = (float*)d_out;                          // [C | rows | cols]

    float* d_partial; cudaGetSymbolAddress((void**)&d_partial, g_partial);
    float* d_pn;      cudaGetSymbolAddress((void**)&d_pn, g_pn);
    float* d_tn;      cudaGetSymbolAddress((void**)&d_tn, g_tn);

    row_sumsq_kernel<<<BN_ROWS, 256>>>(pred_masks, d_pn, HW);
    row_sumsq_kernel<<<T_TGT, 256>>>(target_masks, d_tn, HW);

    dim3 ggrid(MBLKS, KSPLIT);
    gemm_mma_kernel<<<ggrid, 256>>>(pred_masks, target_masks, d_partial);

    finalize_kernel<<<(BN_ROWS * T_TGT + 255) / 256, 256>>>(d_partial, d_pn, d_tn,
                                                            pred_logits, tgt_ids, out);

    lsa_kernel<<<B_IMG, 32>>>(out,
                              out + BN_ROWS * T_TGT,
                              out + BN_ROWS * T_TGT + B_IMG * M_TGT);
}

// round 4
// speedup vs baseline: 2.6719x; 1.1414x over previous
#include <cuda_runtime.h>
#include <cstdint>

// ---------------- problem dimensions (fixed by the dataset) ----------------
#define B_IMG   8
#define N_PRED  100
#define T_TGT   160
#define M_TGT   20
#define K_CLS   80
#define HW      25600
#define BN_ROWS 800

// ---------------- mma.sync tf32 GEMM tiling ----------------
#define KSPLIT  20
#define KCHUNK  1280             // HW / KSPLIT
#define BK      16
#define NIT     (KCHUNK / BK)    // 80
#define MTILE   128
#define MBLKS   7                // ceil(800/128)
#define LDA_S   20               // smem row stride in floats (16 + 4 pad)
#define STAGE_F 5760             // floats per stage: 128*20 + 160*20
#define NSTAGE  3
#define SMEM_BYTES (NSTAGE * STAGE_F * 4)   // 69120

// ---------------- scratch (no allocations allowed) ----------------
__device__ float g_partial[KSPLIT * BN_ROWS * T_TGT];   // 10.24 MB, [ks][row][col]
__device__ float g_pnp[KSPLIT * BN_ROWS];
__device__ float g_tnp[KSPLIT * T_TGT];
__device__ float g_pn[BN_ROWS];
__device__ float g_tn[T_TGT];

// ---------------- helpers ----------------
__device__ __forceinline__ uint32_t smem_u32(const void* p) {
    uint32_t a;
    asm("{ .reg .u64 t; cvta.to.shared.u64 t, %1; cvt.u32.u64 %0, t; }" : "=r"(a) : "l"(p));
    return a;
}
__device__ __forceinline__ void cp16(uint32_t dst, const void* src, int sz) {
    asm volatile("cp.async.cg.shared.global [%0], [%1], 16, %2;"
                 :: "r"(dst), "l"(src), "r"(sz) : "memory");
}
__device__ __forceinline__ void cp_commit() {
    asm volatile("cp.async.commit_group;" ::: "memory");
}
__device__ __forceinline__ void mma_tf32(float* c, const uint32_t* a, const uint32_t* b) {
    asm volatile(
        "mma.sync.aligned.m16n8k8.row.col.f32.tf32.tf32.f32 "
        "{%0,%1,%2,%3}, {%4,%5,%6,%7}, {%8,%9}, {%0,%1,%2,%3};"
        : "+f"(c[0]), "+f"(c[1]), "+f"(c[2]), "+f"(c[3])
        : "r"(a[0]), "r"(a[1]), "r"(a[2]), "r"(a[3]), "r"(b[0]), "r"(b[1]));
}

// ---------------- tf32 mma.sync split-K GEMM + fused sumsq ----------------
// P[ks][row][col] = A[row, kChunk] . B[col, kChunk]^T
// g_pnp[ks][row]  = sum_kChunk A[row,k]^2          (per M-block rows)
// g_tnp[ks][col]  = sum_kChunk B[col,k]^2          (cols sliced col%7==blockIdx.x)
__global__ void __launch_bounds__(256, 1)
gemm_mma_kernel(const float* __restrict__ A, const float* __restrict__ Bm,
                float* __restrict__ P, float* __restrict__ pnp, float* __restrict__ tnp)
{
    extern __shared__ __align__(16) float dsm[];

    const int tid   = threadIdx.x;
    const int wid   = tid >> 5;
    const int lane  = tid & 31;
    const int gid   = lane >> 2;     // 0..7
    const int tig   = lane & 3;      // 0..3
    const int warpM = wid >> 1;      // 0..3 -> 32 rows each
    const int warpN = wid & 1;       // 0..1 -> 80 cols each
    const int bx    = blockIdx.x;
    const int by    = blockIdx.y;
    const int mBase = bx * MTILE;
    const int kBase = by * KCHUNK;

    float acc[2][10][4];
#pragma unroll
    for (int tm = 0; tm < 2; tm++)
#pragma unroll
        for (int tn = 0; tn < 10; tn++)
#pragma unroll
            for (int i = 0; i < 4; i++) acc[tm][tn][i] = 0.f;

    const uint32_t sbase = smem_u32(dsm);

    // ---- async tile loader ----
    auto issue = [&](int t) {
        const int buf = t % NSTAGE;
        const uint32_t sb = sbase + buf * (STAGE_F * 4);
        const int kOff = kBase + t * BK;
#pragma unroll
        for (int i = 0; i < 2; ++i) {
            const int f = tid * 2 + i;
            const int row = f >> 2, kq = f & 3;
            const int grow = mBase + row;
            const int ok = grow < BN_ROWS;
            const float* src = A + (size_t)(ok ? grow : 0) * HW + kOff + kq * 4;
            cp16(sb + row * (LDA_S * 4) + kq * 16, src, ok ? 16 : 0);
        }
#pragma unroll
        for (int i = 0; i < 3; ++i) {
            const int f = tid + i * 256;
            if (f < T_TGT * 4) {
                const int row = f >> 2, kq = f & 3;
                cp16(sb + (MTILE * LDA_S * 4) + row * (LDA_S * 4) + kq * 16,
                     Bm + (size_t)row * HW + kOff + kq * 4, 16);
            }
        }
        cp_commit();
    };

    // sumsq bookkeeping
    const int sq_arow = tid >> 1;              // 0..127
    const int sq_akh  = (tid & 1) * 8;         // 0 or 8
    const int sq_m    = tid >> 4;              // 0..15
    const int sq_k    = tid & 15;
    const int sq_br0  = bx + 7 * sq_m;               // always < 160
    const int sq_br1  = bx + 7 * (sq_m + 16);        // may be >= 160
    const bool sq_b1ok = (sq_br1 < T_TGT);
    float accA = 0.f, accB0 = 0.f, accB1 = 0.f;

    issue(0);
    issue(1);

    for (int t = 0; t < NIT; ++t) {
        if (t + 2 < NIT) issue(t + 2);
        if (t < NIT - 2)      asm volatile("cp.async.wait_group 2;" ::: "memory");
        else if (t == NIT - 2) asm volatile("cp.async.wait_group 1;" ::: "memory");
        else                   asm volatile("cp.async.wait_group 0;" ::: "memory");
        __syncthreads();

        const int buf = t % NSTAGE;
        const float* asf = dsm + buf * STAGE_F;
        const float* bsf = asf + MTILE * LDA_S;
        const uint32_t* as = (const uint32_t*)asf;
        const uint32_t* bs = (const uint32_t*)bsf;

        // fused sumsq from smem
        {
            const float2* a2 = (const float2*)(asf + sq_arow * LDA_S + sq_akh);
#pragma unroll
            for (int i = 0; i < 4; ++i) {
                float2 v = a2[i];
                accA += v.x * v.x + v.y * v.y;
            }
            float b0 = bsf[sq_br0 * LDA_S + sq_k];
            accB0 += b0 * b0;
            if (sq_b1ok) {
                float b1 = bsf[sq_br1 * LDA_S + sq_k];
                accB1 += b1 * b1;
            }
        }

#pragma unroll
        for (int s = 0; s < 2; ++s) {           // two k=8 steps per BK=16
            uint32_t af[2][4], bf[10][2];
#pragma unroll
            for (int tm = 0; tm < 2; tm++) {
                const int r0 = warpM * 32 + tm * 16 + gid;
                const int k0 = s * 8 + tig;
                af[tm][0] = as[r0 * LDA_S + k0];
                af[tm][1] = as[(r0 + 8) * LDA_S + k0];
                af[tm][2] = as[r0 * LDA_S + k0 + 4];
                af[tm][3] = as[(r0 + 8) * LDA_S + k0 + 4];
            }
#pragma unroll
            for (int tn = 0; tn < 10; tn++) {
                const int n = warpN * 80 + tn * 8 + gid;
                const int k0 = s * 8 + tig;
                bf[tn][0] = bs[n * LDA_S + k0];
                bf[tn][1] = bs[n * LDA_S + k0 + 4];
            }
#pragma unroll
            for (int tm = 0; tm < 2; tm++)
#pragma unroll
                for (int tn = 0; tn < 10; tn++)
                    mma_tf32(acc[tm][tn], af[tm], bf[tn]);
        }
        __syncthreads();
    }

    // ---- sumsq reduction (smem reuse after mainloop) ----
    dsm[tid] = accA;                 // A partials: 2 per row
    dsm[256 + tid] = accB0;          // B rows m=0..15, slot m*16+k == tid
    dsm[512 + tid] = sq_b1ok ? accB1 : 0.f;
    __syncthreads();
    if (tid < 128) {
        const float s = dsm[2 * tid] + dsm[2 * tid + 1];
        const int gr = mBase + tid;
        if (gr < BN_ROWS) pnp[by * BN_ROWS + gr] = s;
    } else if (tid < 160) {
        const int m = tid - 128;
        const int r = bx + 7 * m;
        if (r < T_TGT) {
            const int base = (m < 16) ? (256 + m * 16) : (512 + (m - 16) * 16);
            float s = 0.f;
#pragma unroll
            for (int k = 0; k < 16; ++k) s += dsm[base + k];
            tnp[by * T_TGT + r] = s;
        }
    }

    // ---- epilogue: write P[ks][row][col] ----
    float* dst = P + (size_t)by * (BN_ROWS * T_TGT);
#pragma unroll
    for (int tm = 0; tm < 2; tm++) {
        const int r0 = mBase + warpM * 32 + tm * 16 + gid;
        const int r1 = r0 + 8;
#pragma unroll
        for (int tn = 0; tn < 10; tn++) {
            const int col = warpN * 80 + tn * 8 + tig * 2;
            if (r0 < BN_ROWS)
                *(float2*)&dst[(size_t)r0 * T_TGT + col] = make_float2(acc[tm][tn][0], acc[tm][tn][1]);
            if (r1 < BN_ROWS)
                *(float2*)&dst[(size_t)r1 * T_TGT + col] = make_float2(acc[tm][tn][2], acc[tm][tn][3]);
        }
    }
}

// ---------------- reduce per-ksplit norms ----------------
__global__ void __launch_bounds__(256) reduce_norms_kernel(const float* __restrict__ pnp,
                                                           const float* __restrict__ tnp,
                                                           float* __restrict__ pn,
                                                           float* __restrict__ tn)
{
    const int t = blockIdx.x * 256 + threadIdx.x;
    if (t < BN_ROWS) {
        float s = 0.f;
#pragma unroll
        for (int ks = 0; ks < KSPLIT; ks++) s += pnp[ks * BN_ROWS + t];
        pn[t] = s;
    } else if (t < BN_ROWS + T_TGT) {
        const int r = t - BN_ROWS;
        float s = 0.f;
#pragma unroll
        for (int ks = 0; ks < KSPLIT; ks++) s += tnp[ks * T_TGT + r];
        tn[r] = s;
    }
}

// ---------------- finalize: dice + focal -> C ----------------
__global__ void __launch_bounds__(256) finalize_kernel(const float* __restrict__ P,
                                                       const float* __restrict__ pn,
                                                       const float* __restrict__ tn,
                                                       const float* __restrict__ logits,
                                                       const int*   __restrict__ ids,
                                                       float* __restrict__ C)
{
    const int idx = blockIdx.x * 256 + threadIdx.x;
    if (idx >= BN_ROWS * T_TGT) return;
    const int bn = idx / T_TGT;
    const int t  = idx - bn * T_TGT;

    float dot = 0.f;
#pragma unroll
    for (int ks = 0; ks < KSPLIT; ks++)
        dot += P[(size_t)ks * (BN_ROWS * T_TGT) + idx];

    const float den = pn[bn] + tn[t];
    const float score = -((2.0f * dot + 1e-4f) / (den + 1e-4f));   // dice score cost

    const int id = ids[t];
    const float x = logits[bn * K_CLS + id];
    float pl;
    if (x >= 0.f) pl = 1.f / (1.f + expf(-x));
    else { float e = expf(x); pl = e / (1.f + e); }
    const float pos = 0.25f * (1.f - pl) * (1.f - pl) * (-logf(pl + 1e-8f));
    const float neg = 0.75f * pl * pl * (-logf(1.f - pl + 1e-8f));

    C[idx] = score * 2.0f + (pos - neg);
}

// ---------------- Jonker-Volgenant LSA, one warp per image ----------------
__device__ __forceinline__ unsigned long long dkey(double d) {
    long long b = __double_as_longlong(d);
    return (unsigned long long)(b >= 0 ? (b ^ 0x8000000000000000LL) : ~b);
}
__device__ __forceinline__ double inv_dkey(unsigned long long k) {
    long long b = (k & 0x8000000000000000ULL) ? (long long)(k ^ 0x8000000000000000ULL)
                                              : ~(long long)k;
    return __longlong_as_double(b);
}

__global__ void __launch_bounds__(32) lsa_kernel(const float* __restrict__ C,
                                                 float* __restrict__ out_rows,
                                                 float* __restrict__ out_cols)
{
    const int b    = blockIdx.x;
    const int lane = threadIdx.x;
    const double INFD = 1e18;

    __shared__ float  c[M_TGT][N_PRED];     // c[t][pred]
    __shared__ double u[M_TGT + 1], v[N_PRED + 1], minv[N_PRED + 1];
    __shared__ int    p[N_PRED + 1], way[N_PRED + 1], used[N_PRED + 1];

    for (int idx = lane; idx < M_TGT * N_PRED; idx += 32) {
        int t = idx / N_PRED, n = idx - t * N_PRED;
        c[t][n] = C[(size_t)b * (N_PRED * T_TGT) + (size_t)n * T_TGT + b * M_TGT + t];
    }
    for (int j = lane; j <= N_PRED; j += 32) { v[j] = 0.0; p[j] = 0; way[j] = 0; }
    if (lane <= M_TGT) u[lane] = 0.0;
    __syncwarp();

    for (int i = 1; i <= M_TGT; ++i) {
        if (lane == 0) p[0] = i;
        for (int j = lane; j <= N_PRED; j += 32) { minv[j] = INFD; used[j] = 0; }
        __syncwarp();

        int j0 = 0;
        while (true) {
            used[j0] = 1;                     // all lanes, same value: benign race,
                                              // self-visibility is program-ordered
            const int i0 = p[j0];
            const double ui0 = u[i0];

            unsigned long long bestKey = 0xFFFFFFFFFFFFFFFFULL;
            int bestJ = N_PRED + 1;
#pragma unroll
            for (int q = 0; q < 4; q++) {
                int j = lane + q * 32;
                if (j >= 1 && j <= N_PRED && !used[j]) {
                    double cur = ((double)c[i0 - 1][j - 1] - ui0) - v[j];
                    double mj = minv[j];
                    if (cur < mj) { minv[j] = cur; way[j] = j0; mj = cur; }
                    unsigned long long key = dkey(mj);
                    if (key < bestKey) { bestKey = key; bestJ = j; }
                }
            }
            for (int off = 16; off > 0; off >>= 1) {
                unsigned long long k2 = __shfl_down_sync(0xffffffff, bestKey, off);
                int j2 = __shfl_down_sync(0xffffffff, bestJ, off);
                if (k2 < bestKey || (k2 == bestKey && j2 < bestJ)) { bestKey = k2; bestJ = j2; }
            }
            bestKey = __shfl_sync(0xffffffff, bestKey, 0);
            bestJ   = __shfl_sync(0xffffffff, bestJ, 0);
            const int j1 = bestJ;
            const double delta = inv_dkey(bestKey);

            __syncwarp();
#pragma unroll
            for (int q = 0; q < 4; q++) {
                int j = lane + q * 32;
                if (j <= N_PRED) {
                    if (used[j]) { u[p[j]] += delta; v[j] -= delta; }
                    else         { minv[j] -= delta; }
                }
            }
            __syncwarp();

            j0 = j1;
            if (p[j0] == 0) break;
        }

        if (lane == 0) {
            int jj = j0;
            while (jj != 0) { int jn = way[jj]; p[jj] = p[jn]; jj = jn; }
        }
        __syncwarp();
    }

    if (lane == 0) {
        int k = 0;
        for (int j = 1; j <= N_PRED; j++) {
            if (p[j] != 0) {
                out_rows[b * M_TGT + k] = (float)(j - 1);
                out_cols[b * M_TGT + k] = (float)(p[j] - 1);
                k++;
            }
        }
    }
}

// ---------------- launch ----------------
extern "C" void kernel_launch(void* const* d_in, const int* in_sizes, int n_in,
                              void* d_out, int out_size)
{
    const float* pred_masks   = (const float*)d_in[0];   // (8,100,160,160)
    const float* pred_logits  = (const float*)d_in[1];   // (8,100,80)
    const float* target_masks = (const float*)d_in[2];   // (160,160,160)
    const int*   tgt_ids      = (const int*)d_in[3];     // (160,)
    float* out = (float*)d_out;                          // [C | rows | cols]

    float* d_partial; cudaGetSymbolAddress((void**)&d_partial, g_partial);
    float* d_pnp;     cudaGetSymbolAddress((void**)&d_pnp, g_pnp);
    float* d_tnp;     cudaGetSymbolAddress((void**)&d_tnp, g_tnp);
    float* d_pn;      cudaGetSymbolAddress((void**)&d_pn, g_pn);
    float* d_tn;      cudaGetSymbolAddress((void**)&d_tn, g_tn);

    cudaFuncSetAttribute(gemm_mma_kernel,
                         cudaFuncAttributeMaxDynamicSharedMemorySize, SMEM_BYTES);

    dim3 ggrid(MBLKS, KSPLIT);
    gemm_mma_kernel<<<ggrid, 256, SMEM_BYTES>>>(pred_masks, target_masks,
                                                d_partial, d_pnp, d_tnp);

    reduce_norms_kernel<<<(BN_ROWS + T_TGT + 255) / 256, 256>>>(d_pnp, d_tnp, d_pn, d_tn);

    finalize_kernel<<<(BN_ROWS * T_TGT + 255) / 256, 256>>>(d_partial, d_pn, d_tn,
                                                            pred_logits, tgt_ids, out);

    lsa_kernel<<<B_IMG, 32>>>(out,
                              out + BN_ROWS * T_TGT,
                              out + BN_ROWS * T_TGT + B_IMG * M_TGT);
}

// round 5
// speedup vs baseline: 3.0383x; 1.1372x over previous
#include <cuda_runtime.h>
#include <cstdint>

// ---------------- problem dimensions (fixed by the dataset) ----------------
#define B_IMG   8
#define N_PRED  100
#define T_TGT   160
#define M_TGT   20
#define K_CLS   80
#define HW      25600
#define BN_ROWS 800

// ---------------- mma.sync tf32 GEMM tiling ----------------
#define KSPLIT  20
#define KCHUNK  1280             // HW / KSPLIT
#define BK      16
#define NIT     (KCHUNK / BK)    // 80
#define MTILE   128
#define MBLKS   7                // ceil(800/128)
#define LDA_S   20               // smem row stride in floats (16 + 4 pad)
#define STAGE_F 5760             // floats per stage: 128*20 + 160*20
#define NSTAGE  4
#define SMEM_BYTES (NSTAGE * STAGE_F * 4)   // 92160

// ---------------- scratch (no allocations allowed) ----------------
__device__ float g_partial[KSPLIT * BN_ROWS * T_TGT];   // 10.24 MB, [ks][row][col]
__device__ float g_pnp[KSPLIT * BN_ROWS];
__device__ float g_tnp[KSPLIT * T_TGT];

// ---------------- helpers ----------------
__device__ __forceinline__ uint32_t smem_u32(const void* p) {
    uint32_t a;
    asm("{ .reg .u64 t; cvta.to.shared.u64 t, %1; cvt.u32.u64 %0, t; }" : "=r"(a) : "l"(p));
    return a;
}
__device__ __forceinline__ void cp16(uint32_t dst, const void* src, int sz) {
    asm volatile("cp.async.cg.shared.global [%0], [%1], 16, %2;"
                 :: "r"(dst), "l"(src), "r"(sz) : "memory");
}
__device__ __forceinline__ void cp_commit() {
    asm volatile("cp.async.commit_group;" ::: "memory");
}
__device__ __forceinline__ void mma_tf32(float* c, const uint32_t* a, const uint32_t* b) {
    asm volatile(
        "mma.sync.aligned.m16n8k8.row.col.f32.tf32.tf32.f32 "
        "{%0,%1,%2,%3}, {%4,%5,%6,%7}, {%8,%9}, {%0,%1,%2,%3};"
        : "+f"(c[0]), "+f"(c[1]), "+f"(c[2]), "+f"(c[3])
        : "r"(a[0]), "r"(a[1]), "r"(a[2]), "r"(a[3]), "r"(b[0]), "r"(b[1]));
}

// ---------------- tf32 mma.sync split-K GEMM + fused sumsq ----------------
__global__ void __launch_bounds__(256, 1)
gemm_mma_kernel(const float* __restrict__ A, const float* __restrict__ Bm,
                float* __restrict__ P, float* __restrict__ pnp, float* __restrict__ tnp)
{
    extern __shared__ __align__(16) float dsm[];

    const int tid   = threadIdx.x;
    const int wid   = tid >> 5;
    const int lane  = tid & 31;
    const int gid   = lane >> 2;     // 0..7
    const int tig   = lane & 3;      // 0..3
    const int warpM = wid >> 1;      // 0..3 -> 32 rows each
    const int warpN = wid & 1;       // 0..1 -> 80 cols each
    const int bx    = blockIdx.x;
    const int by    = blockIdx.y;
    const int mBase = bx * MTILE;
    const int kBase = by * KCHUNK;

    float acc[2][10][4];
#pragma unroll
    for (int tm = 0; tm < 2; tm++)
#pragma unroll
        for (int tn = 0; tn < 10; tn++)
#pragma unroll
            for (int i = 0; i < 4; i++) acc[tm][tn][i] = 0.f;

    const uint32_t sbase = smem_u32(dsm);

    auto issue = [&](int t) {
        const int buf = t % NSTAGE;
        const uint32_t sb = sbase + buf * (STAGE_F * 4);
        const int kOff = kBase + t * BK;
#pragma unroll
        for (int i = 0; i < 2; ++i) {
            const int f = tid * 2 + i;
            const int row = f >> 2, kq = f & 3;
            const int grow = mBase + row;
            const int ok = grow < BN_ROWS;
            const float* src = A + (size_t)(ok ? grow : 0) * HW + kOff + kq * 4;
            cp16(sb + row * (LDA_S * 4) + kq * 16, src, ok ? 16 : 0);
        }
#pragma unroll
        for (int i = 0; i < 3; ++i) {
            const int f = tid + i * 256;
            if (f < T_TGT * 4) {
                const int row = f >> 2, kq = f & 3;
                cp16(sb + (MTILE * LDA_S * 4) + row * (LDA_S * 4) + kq * 16,
                     Bm + (size_t)row * HW + kOff + kq * 4, 16);
            }
        }
        cp_commit();
    };

    // fused sumsq bookkeeping
    const int sq_arow = tid >> 1;              // 0..127
    const int sq_akh  = (tid & 1) * 8;         // 0 or 8
    const int sq_m    = tid >> 4;              // 0..15
    const int sq_k    = tid & 15;
    const int sq_br0  = bx + 7 * sq_m;               // < 160 always
    const int sq_br1  = bx + 7 * (sq_m + 16);        // may be >= 160
    const bool sq_b1ok = (sq_br1 < T_TGT);
    float accA = 0.f, accB0 = 0.f, accB1 = 0.f;

    issue(0); issue(1); issue(2);

    for (int t = 0; t < NIT; ++t) {
        if (t < NIT - 3)       asm volatile("cp.async.wait_group 2;" ::: "memory");
        else if (t == NIT - 3) asm volatile("cp.async.wait_group 2;" ::: "memory");
        else if (t == NIT - 2) asm volatile("cp.async.wait_group 1;" ::: "memory");
        else                   asm volatile("cp.async.wait_group 0;" ::: "memory");
        __syncthreads();
        if (t + 3 < NIT) issue(t + 3);

        const int buf = t % NSTAGE;
        const float* asf = dsm + buf * STAGE_F;
        const float* bsf = asf + MTILE * LDA_S;
        const uint32_t* as = (const uint32_t*)asf;
        const uint32_t* bs = (const uint32_t*)bsf;

        // fused sumsq from smem
        {
            const float2* a2 = (const float2*)(asf + sq_arow * LDA_S + sq_akh);
#pragma unroll
            for (int i = 0; i < 4; ++i) {
                float2 v = a2[i];
                accA += v.x * v.x + v.y * v.y;
            }
            float b0 = bsf[sq_br0 * LDA_S + sq_k];
            accB0 += b0 * b0;
            if (sq_b1ok) {
                float b1 = bsf[sq_br1 * LDA_S + sq_k];
                accB1 += b1 * b1;
            }
        }

#pragma unroll
        for (int s = 0; s < 2; ++s) {
            uint32_t af[2][4], bf[10][2];
#pragma unroll
            for (int tm = 0; tm < 2; tm++) {
                const int r0 = warpM * 32 + tm * 16 + gid;
                const int k0 = s * 8 + tig;
                af[tm][0] = as[r0 * LDA_S + k0];
                af[tm][1] = as[(r0 + 8) * LDA_S + k0];
                af[tm][2] = as[r0 * LDA_S + k0 + 4];
                af[tm][3] = as[(r0 + 8) * LDA_S + k0 + 4];
            }
#pragma unroll
            for (int tn = 0; tn < 10; tn++) {
                const int n = warpN * 80 + tn * 8 + gid;
                const int k0 = s * 8 + tig;
                bf[tn][0] = bs[n * LDA_S + k0];
                bf[tn][1] = bs[n * LDA_S + k0 + 4];
            }
#pragma unroll
            for (int tm = 0; tm < 2; tm++)
#pragma unroll
                for (int tn = 0; tn < 10; tn++)
                    mma_tf32(acc[tm][tn], af[tm], bf[tn]);
        }
    }
    __syncthreads();   // protect smem reuse below

    // ---- sumsq reduction (smem reuse after mainloop) ----
    dsm[tid] = accA;
    dsm[256 + tid] = accB0;
    dsm[512 + tid] = sq_b1ok ? accB1 : 0.f;
    __syncthreads();
    if (tid < 128) {
        const float s = dsm[2 * tid] + dsm[2 * tid + 1];
        const int gr = mBase + tid;
        if (gr < BN_ROWS) pnp[by * BN_ROWS + gr] = s;
    } else if (tid < 160) {
        const int m = tid - 128;
        const int r = bx + 7 * m;
        if (r < T_TGT) {
            const int base = (m < 16) ? (256 + m * 16) : (512 + (m - 16) * 16);
            float s = 0.f;
#pragma unroll
            for (int k = 0; k < 16; ++k) s += dsm[base + k];
            tnp[by * T_TGT + r] = s;
        }
    }

    // ---- epilogue: write P[ks][row][col] ----
    float* dst = P + (size_t)by * (BN_ROWS * T_TGT);
#pragma unroll
    for (int tm = 0; tm < 2; tm++) {
        const int r0 = mBase + warpM * 32 + tm * 16 + gid;
        const int r1 = r0 + 8;
#pragma unroll
        for (int tn = 0; tn < 10; tn++) {
            const int col = warpN * 80 + tn * 8 + tig * 2;
            if (r0 < BN_ROWS)
                *(float2*)&dst[(size_t)r0 * T_TGT + col] = make_float2(acc[tm][tn][0], acc[tm][tn][1]);
            if (r1 < BN_ROWS)
                *(float2*)&dst[(size_t)r1 * T_TGT + col] = make_float2(acc[tm][tn][2], acc[tm][tn][3]);
        }
    }
}

// ---------------- finalize: ksplit-sum + norms + dice + focal -> C ----------------
__global__ void __launch_bounds__(256) finalize_kernel(const float* __restrict__ P,
                                                       const float* __restrict__ pnp,
                                                       const float* __restrict__ tnp,
                                                       const float* __restrict__ logits,
                                                       const int*   __restrict__ ids,
                                                       float* __restrict__ C)
{
    const int idx = blockIdx.x * 256 + threadIdx.x;
    if (idx >= BN_ROWS * T_TGT) return;
    const int bn = idx / T_TGT;
    const int t  = idx - bn * T_TGT;

    float dot = 0.f, pnv = 0.f, tnv = 0.f;
#pragma unroll
    for (int ks = 0; ks < KSPLIT; ks++) {
        dot += P[(size_t)ks * (BN_ROWS * T_TGT) + idx];
        pnv += pnp[ks * BN_ROWS + bn];
        tnv += tnp[ks * T_TGT + t];
    }

    const float den = pnv + tnv;
    const float score = -((2.0f * dot + 1e-4f) / (den + 1e-4f));

    const int id = ids[t];
    const float x = logits[bn * K_CLS + id];
    float pl;
    if (x >= 0.f) pl = 1.f / (1.f + expf(-x));
    else { float e = expf(x); pl = e / (1.f + e); }
    const float pos = 0.25f * (1.f - pl) * (1.f - pl) * (-logf(pl + 1e-8f));
    const float neg = 0.75f * pl * pl * (-logf(1.f - pl + 1e-8f));

    C[idx] = score * 2.0f + (pos - neg);
}

// ---------------- Jonker-Volgenant LSA, register-resident, one warp/image ----------------
__device__ __forceinline__ unsigned long long dkey(double d) {
    long long b = __double_as_longlong(d);
    return (unsigned long long)(b >= 0 ? (b ^ 0x8000000000000000LL) : ~b);
}
__device__ __forceinline__ double inv_dkey(unsigned long long k) {
    long long b = (k & 0x8000000000000000ULL) ? (long long)(k ^ 0x8000000000000000ULL)
                                              : ~(long long)k;
    return __longlong_as_double(b);
}

__global__ void __launch_bounds__(32) lsa_kernel(const float* __restrict__ C,
                                                 float* __restrict__ out_rows,
                                                 float* __restrict__ out_cols)
{
    const int b    = blockIdx.x;
    const int lane = threadIdx.x;
    const double INFD = 1e18;

    __shared__ double c[M_TGT][N_PRED];      // f64 copy (kills F2F on hot path)
    __shared__ double u[M_TGT + 1];
    __shared__ int    p[N_PRED + 1];
    __shared__ int    way[N_PRED + 1];

    for (int idx = lane; idx < M_TGT * N_PRED; idx += 32) {
        int t = idx / N_PRED, n = idx - t * N_PRED;
        c[t][n] = (double)C[(size_t)b * (N_PRED * T_TGT) + (size_t)n * T_TGT + b * M_TGT + t];
    }
    for (int j = lane; j <= N_PRED; j += 32) { p[j] = 0; way[j] = 0; }
    if (lane <= M_TGT) u[lane] = 0.0;

    // lane owns columns j = 1+lane+32q
    const int jq0 = 1 + lane, jq1 = 33 + lane, jq2 = 65 + lane, jq3 = 97 + lane;
    const bool v3 = (jq3 <= N_PRED);
    double v_r0 = 0, v_r1 = 0, v_r2 = 0, v_r3 = 0;
    double m_r0, m_r1, m_r2, m_r3;
    bool  u_r0, u_r1, u_r2, u_r3;
    __syncwarp();

    for (int i = 1; i <= M_TGT; ++i) {
        if (lane == 0) p[0] = i;
        m_r0 = m_r1 = m_r2 = m_r3 = INFD;
        u_r0 = u_r1 = u_r2 = u_r3 = false;
        __syncwarp();

        int j0 = 0;
        while (true) {
            // mark j0 used (owner lane only; j0=0 has no owner)
            u_r0 |= (jq0 == j0); u_r1 |= (jq1 == j0);
            u_r2 |= (jq2 == j0); u_r3 |= (jq3 == j0);

            const int i0 = p[j0];
            const double ui0 = u[i0];
            const double* crow = c[i0 - 1];

            unsigned long long bestKey = 0xFFFFFFFFFFFFFFFFULL;
            int bestJ = 0x7FFFFFFF;
            // relax + local argmin (ascending j => first-index tie-break)
            if (!u_r0) {
                double cur = (crow[jq0 - 1] - ui0) - v_r0;
                if (cur < m_r0) { m_r0 = cur; way[jq0] = j0; }
                unsigned long long k = dkey(m_r0);
                if (k < bestKey) { bestKey = k; bestJ = jq0; }
            }
            if (!u_r1) {
                double cur = (crow[jq1 - 1] - ui0) - v_r1;
                if (cur < m_r1) { m_r1 = cur; way[jq1] = j0; }
                unsigned long long k = dkey(m_r1);
                if (k < bestKey) { bestKey = k; bestJ = jq1; }
            }
            if (!u_r2) {
                double cur = (crow[jq2 - 1] - ui0) - v_r2;
                if (cur < m_r2) { m_r2 = cur; way[jq2] = j0; }
                unsigned long long k = dkey(m_r2);
                if (k < bestKey) { bestKey = k; bestJ = jq2; }
            }
            if (v3 && !u_r3) {
                double cur = (crow[jq3 - 1] - ui0) - v_r3;
                if (cur < m_r3) { m_r3 = cur; way[jq3] = j0; }
                unsigned long long k = dkey(m_r3);
                if (k < bestKey) { bestKey = k; bestJ = jq3; }
            }

            // exact u64 lexicographic argmin via 3x redux.min.u32
            const unsigned hi = (unsigned)(bestKey >> 32);
            const unsigned minHi = __reduce_min_sync(0xffffffff, hi);
            const unsigned lo = (hi == minHi) ? (unsigned)bestKey : 0xffffffffu;
            const unsigned minLo = __reduce_min_sync(0xffffffff, lo);
            const unsigned jc = (hi == minHi && (unsigned)bestKey == minLo)
                                ? (unsigned)bestJ : 0x7fffffffu;
            const int j1 = (int)__reduce_min_sync(0xffffffff, jc);
            const double delta = inv_dkey(((unsigned long long)minHi << 32) | minLo);

            // updates: used -> u[p[j]] += delta, v -= delta ; free -> minv -= delta
            if (u_r0) { u[p[jq0]] += delta; v_r0 -= delta; } else { m_r0 -= delta; }
            if (u_r1) { u[p[jq1]] += delta; v_r1 -= delta; } else { m_r1 -= delta; }
            if (u_r2) { u[p[jq2]] += delta; v_r2 -= delta; } else { m_r2 -= delta; }
            if (v3) { if (u_r3) { u[p[jq3]] += delta; v_r3 -= delta; } else { m_r3 -= delta; } }
            if (lane == 0) u[p[0]] += delta;      // virtual column 0 (current row i)

            __syncwarp();                         // u writes visible before next reads
            j0 = j1;
            if (p[j0] == 0) break;
        }

        if (lane == 0) {                          // augment along way
            int jj = j0;
            while (jj != 0) { int jn = way[jj]; p[jj] = p[jn]; jj = jn; }
        }
        __syncwarp();
    }

    if (lane == 0) {
        int k = 0;
        for (int j = 1; j <= N_PRED; j++) {
            if (p[j] != 0) {
                out_rows[b * M_TGT + k] = (float)(j - 1);
                out_cols[b * M_TGT + k] = (float)(p[j] - 1);
                k++;
            }
        }
    }
}

// ---------------- launch ----------------
extern "C" void kernel_launch(void* const* d_in, const int* in_sizes, int n_in,
                              void* d_out, int out_size)
{
    const float* pred_masks   = (const float*)d_in[0];   // (8,100,160,160)
    const float* pred_logits  = (const float*)d_in[1];   // (8,100,80)
    const float* target_masks = (const float*)d_in[2];   // (160,160,160)
    const int*   tgt_ids      = (const int*)d_in[3];     // (160,)
    float* out = (float*)d_out;                          // [C | rows | cols]

    float* d_partial; cudaGetSymbolAddress((void**)&d_partial, g_partial);
    float* d_pnp;     cudaGetSymbolAddress((void**)&d_pnp, g_pnp);
    float* d_tnp;     cudaGetSymbolAddress((void**)&d_tnp, g_tnp);

    cudaFuncSetAttribute(gemm_mma_kernel,
                         cudaFuncAttributeMaxDynamicSharedMemorySize, SMEM_BYTES);

    dim3 ggrid(MBLKS, KSPLIT);
    gemm_mma_kernel<<<ggrid, 256, SMEM_BYTES>>>(pred_masks, target_masks,
                                                d_partial, d_pnp, d_tnp);

    finalize_kernel<<<(BN_ROWS * T_TGT + 255) / 256, 256>>>(d_partial, d_pnp, d_tnp,
                                                            pred_logits, tgt_ids, out);

    lsa_kernel<<<B_IMG, 32>>>(out,
                              out + BN_ROWS * T_TGT,
                              out + BN_ROWS * T_TGT + B_IMG * M_TGT);
}